// round 1
// baseline (speedup 1.0000x reference)
#include <cuda_runtime.h>
#include <math.h>

#define B_    4
#define DE    128
#define DO    512
#define THW   10240
#define HW    1024
#define NCHUNK 40          // t-chunks of 256 for softmax partial sums
#define SCALE 0.08838834764831845f   // 1/sqrt(128)
#define INV2SIG2 (1.0f/18.0f)        // 1/(2*3^2)

// ---- device scratch (no allocations allowed) ----
__device__ float  g_p[(size_t)B_ * THW * HW];     // correlation matrix p (168 MB)
__device__ float2 g_center[B_ * THW];             // argmax gaussian centers (cx, cy)
__device__ float  g_part[B_ * NCHUNK * HW];       // partial softmax sums
__device__ float  g_inv[B_ * HW];                 // 1/sum per (b,q)

// ============================================================
// Kernel 1: p[b,t,q] = (1/sqrt(De)) * sum_d mi[b,d,t] * qi[b,d,q]
// A = mi [De][THW] row-major (contiguous in t), Bq = qi [De][HW]
// 128x128x16 tile, 256 threads, 8x8 per thread.
// ============================================================
__global__ void __launch_bounds__(256) gemm_p_kernel(
    const float* __restrict__ mi, const float* __restrict__ qi,
    float* __restrict__ p)
{
    const int b = blockIdx.z;
    const float* A  = mi + (size_t)b * DE * THW;
    const float* Bq = qi + (size_t)b * DE * HW;
    float* C        = p  + (size_t)b * THW * HW;
    const int t0 = blockIdx.y * 128;
    const int q0 = blockIdx.x * 128;

    __shared__ float As[16][128];
    __shared__ float Bs[16][128];

    const int tid = threadIdx.x;
    const int tx = tid & 15;   // 16 cols of threads
    const int ty = tid >> 4;   // 16 rows of threads
    float acc[8][8];
    #pragma unroll
    for (int i = 0; i < 8; i++)
        #pragma unroll
        for (int j = 0; j < 8; j++) acc[i][j] = 0.f;

    for (int k0 = 0; k0 < DE; k0 += 16) {
        #pragma unroll
        for (int i = 0; i < 2; i++) {
            int idx = tid + i * 256;       // 0..511
            int kk = idx >> 5;             // 0..15
            int mm = (idx & 31) << 2;      // 0..124
            *(float4*)&As[kk][mm] =
                *(const float4*)(A + (size_t)(k0 + kk) * THW + t0 + mm);
            *(float4*)&Bs[kk][mm] =
                *(const float4*)(Bq + (size_t)(k0 + kk) * HW + q0 + mm);
        }
        __syncthreads();
        #pragma unroll
        for (int k = 0; k < 16; k++) {
            float ar[8], br[8];
            #pragma unroll
            for (int i = 0; i < 8; i++) ar[i] = As[k][ty * 8 + i];
            #pragma unroll
            for (int j = 0; j < 8; j++) br[j] = Bs[k][tx * 8 + j];
            #pragma unroll
            for (int i = 0; i < 8; i++)
                #pragma unroll
                for (int j = 0; j < 8; j++)
                    acc[i][j] += ar[i] * br[j];
        }
        __syncthreads();
    }
    #pragma unroll
    for (int i = 0; i < 8; i++) {
        size_t row = (size_t)(t0 + ty * 8 + i) * HW + q0 + tx * 8;
        #pragma unroll
        for (int j = 0; j < 8; j += 4) {
            float4 v = make_float4(acc[i][j] * SCALE, acc[i][j+1] * SCALE,
                                   acc[i][j+2] * SCALE, acc[i][j+3] * SCALE);
            *(float4*)(C + row + j) = v;
        }
    }
}

// ============================================================
// Kernel 2: argmax over q (1024 contiguous) per (b,t) row; first-index ties.
// One warp per row.
// ============================================================
__global__ void __launch_bounds__(256) argmax_kernel(const float* __restrict__ p)
{
    int gwarp = (blockIdx.x * 256 + threadIdx.x) >> 5;
    int lane  = threadIdx.x & 31;
    if (gwarp >= B_ * THW) return;
    const float* row = p + (size_t)gwarp * HW;

    float best = -3.4e38f;
    int bi = 0;
    #pragma unroll 4
    for (int i = lane; i < HW; i += 32) {
        float v = row[i];
        if (v > best) { best = v; bi = i; }   // increasing i -> keeps first max
    }
    #pragma unroll
    for (int off = 16; off > 0; off >>= 1) {
        float ov = __shfl_down_sync(0xffffffffu, best, off);
        int   oi = __shfl_down_sync(0xffffffffu, bi,   off);
        if (ov > best || (ov == best && oi < bi)) { best = ov; bi = oi; }
    }
    if (lane == 0)
        g_center[gwarp] = make_float2((float)(bi & 31), (float)(bi >> 5));
}

// ============================================================
// Kernel 3a: e[b,t,q] = exp(p[b,t,q] - d^2(t,q)/(2 sigma^2)); partial sums
// over 256-t chunks. (softmax normalizer cancels against gaussian renorm)
// ============================================================
__global__ void __launch_bounds__(256) exp_partial_kernel(
    const float* __restrict__ p, float* __restrict__ e)
{
    const int b  = blockIdx.z;
    const int q  = blockIdx.x * 256 + threadIdx.x;
    const int t0 = blockIdx.y * 256;
    const float qx = (float)(q & 31);
    const float qy = (float)(q >> 5);

    const float2* cen = g_center + (size_t)b * THW + t0;
    const float*  pc  = p + ((size_t)b * THW + t0) * HW + q;
    float*        ec  = e + ((size_t)b * THW + t0) * HW + q;

    float s = 0.f;
    #pragma unroll 4
    for (int t = 0; t < 256; t++) {
        float2 c = cen[t];
        float dx = qx - c.x, dy = qy - c.y;
        float v = __expf(pc[(size_t)t * HW] - (dx * dx + dy * dy) * INV2SIG2);
        ec[(size_t)t * HW] = v;
        s += v;
    }
    g_part[((size_t)b * NCHUNK + blockIdx.y) * HW + q] = s;
}

// Kernel 3b: reduce partials -> g_inv (deterministic fixed order)
__global__ void __launch_bounds__(256) inv_kernel()
{
    int i = blockIdx.x * 256 + threadIdx.x;   // 0..4095 = b*HW+q
    int b = i >> 10, q = i & 1023;
    float s = 0.f;
    #pragma unroll
    for (int c = 0; c < NCHUNK; c++)
        s += g_part[((size_t)b * NCHUNK + c) * HW + q];
    g_inv[i] = 1.0f / s;
}

// Kernel 3c: p_w = e * inv[b,q]  (in place, vectorized)
__global__ void __launch_bounds__(256) scale_kernel(float* __restrict__ e)
{
    const size_t total4 = (size_t)B_ * THW * HW / 4;
    const size_t stride = (size_t)gridDim.x * 256;
    for (size_t i = blockIdx.x * 256ull + threadIdx.x; i < total4; i += stride) {
        float4 v = ((float4*)e)[i];
        size_t q4 = i & 255;                         // HW/4 = 256 (pow2)
        size_t b  = i / ((size_t)THW * HW / 4);
        float4 inv = ((const float4*)g_inv)[b * 256 + q4];
        v.x *= inv.x; v.y *= inv.y; v.z *= inv.z; v.w *= inv.w;
        ((float4*)e)[i] = v;
    }
}

// ============================================================
// Kernel 4: mem[b,o,q] = sum_t mo[b,o,t] * p_w[b,t,q]
// A = mo [Do][THW] row-major (contiguous in t=k), B = p_w [THW][HW]
// writes directly into out[b, o, :] (first half of channel dim).
// ============================================================
__global__ void __launch_bounds__(256) gemm_mem_kernel(
    const float* __restrict__ mo, const float* __restrict__ pw,
    float* __restrict__ out)
{
    const int b = blockIdx.z;
    const float* A  = mo + (size_t)b * DO * THW;
    const float* Bm = pw + (size_t)b * THW * HW;
    float* C        = out + (size_t)b * 2 * DO * HW;
    const int o0 = blockIdx.y * 128;
    const int q0 = blockIdx.x * 128;

    __shared__ float As[16][128];
    __shared__ float Bs[16][128];

    const int tid = threadIdx.x;
    const int tx = tid & 15;
    const int ty = tid >> 4;
    float acc[8][8];
    #pragma unroll
    for (int i = 0; i < 8; i++)
        #pragma unroll
        for (int j = 0; j < 8; j++) acc[i][j] = 0.f;

    for (int k0 = 0; k0 < THW; k0 += 16) {
        #pragma unroll
        for (int i = 0; i < 2; i++) {
            int idx = tid + i * 256;          // 0..511
            // A: row mm (o), 4 k's -> transpose into As[k][m]
            int mm = idx >> 2;                // 0..127
            int kk = (idx & 3) << 2;          // 0,4,8,12
            float4 a = *(const float4*)(A + (size_t)(o0 + mm) * THW + k0 + kk);
            As[kk + 0][mm] = a.x; As[kk + 1][mm] = a.y;
            As[kk + 2][mm] = a.z; As[kk + 3][mm] = a.w;
            // B: row kb (t), contiguous in q
            int kb = idx >> 5;
            int nb = (idx & 31) << 2;
            *(float4*)&Bs[kb][nb] =
                *(const float4*)(Bm + (size_t)(k0 + kb) * HW + q0 + nb);
        }
        __syncthreads();
        #pragma unroll
        for (int k = 0; k < 16; k++) {
            float ar[8], br[8];
            #pragma unroll
            for (int i = 0; i < 8; i++) ar[i] = As[k][ty * 8 + i];
            #pragma unroll
            for (int j = 0; j < 8; j++) br[j] = Bs[k][tx * 8 + j];
            #pragma unroll
            for (int i = 0; i < 8; i++)
                #pragma unroll
                for (int j = 0; j < 8; j++)
                    acc[i][j] += ar[i] * br[j];
        }
        __syncthreads();
    }
    #pragma unroll
    for (int i = 0; i < 8; i++) {
        size_t row = (size_t)(o0 + ty * 8 + i) * HW + q0 + tx * 8;
        #pragma unroll
        for (int j = 0; j < 8; j += 4) {
            float4 v = make_float4(acc[i][j], acc[i][j+1], acc[i][j+2], acc[i][j+3]);
            *(float4*)(C + row + j) = v;
        }
    }
}

// Kernel 5: copy q_out into second half of channel dim of out
__global__ void __launch_bounds__(256) copy_qout_kernel(
    const float* __restrict__ q_out, float* __restrict__ out)
{
    const size_t per_b4 = (size_t)DO * HW / 4;     // 131072 float4 per batch
    const size_t total4 = (size_t)B_ * per_b4;
    const size_t stride = (size_t)gridDim.x * 256;
    const float4* src = (const float4*)q_out;
    float4* dst = (float4*)out;
    for (size_t i = blockIdx.x * 256ull + threadIdx.x; i < total4; i += stride) {
        size_t b = i / per_b4;
        size_t r = i - b * per_b4;
        dst[b * 2 * per_b4 + per_b4 + r] = src[i];
    }
}

// ============================================================
extern "C" void kernel_launch(void* const* d_in, const int* in_sizes, int n_in,
                              void* d_out, int out_size)
{
    const float* m_in  = (const float*)d_in[0];  // [B,De,T,H,W]
    const float* m_out = (const float*)d_in[1];  // [B,Do,T,H,W]
    const float* q_in  = (const float*)d_in[2];  // [B,De,H,W]
    const float* q_out = (const float*)d_in[3];  // [B,Do,H,W]
    float* out = (float*)d_out;

    float* p = nullptr;
    cudaGetSymbolAddress((void**)&p, g_p);

    // p_w output region: after mem_out (B * 2*Do * H * W floats), if present
    const size_t memout_elems = (size_t)B_ * 2 * DO * HW;          // 4,194,304
    const size_t pw_elems     = (size_t)B_ * THW * HW;             // 41,943,040
    float* e = ((size_t)out_size >= memout_elems + pw_elems)
                   ? (out + memout_elems)
                   : p;   // fallback: keep p_w in scratch (in-place over p)

    // 1) correlation GEMM
    dim3 g1(HW / 128, THW / 128, B_);            // (8, 80, 4)
    gemm_p_kernel<<<g1, 256>>>(m_in, q_in, p);

    // 2) argmax -> gaussian centers
    argmax_kernel<<<(B_ * THW) / 8, 256>>>(p);

    // 3) fused gaussian-softmax: exp pass + reduce + scale
    dim3 g3(HW / 256, NCHUNK, B_);               // (4, 40, 4)
    exp_partial_kernel<<<g3, 256>>>(p, e);
    inv_kernel<<<(B_ * HW) / 256, 256>>>();
    scale_kernel<<<1184, 256>>>(e);

    // 4) memory readout GEMM -> out[:, :Do]
    dim3 g4(HW / 128, DO / 128, B_);             // (8, 4, 4)
    gemm_mem_kernel<<<g4, 256>>>(m_out, e, out);

    // 5) out[:, Do:] = q_out
    copy_qout_kernel<<<512, 256>>>(q_out, out);
}